// round 1
// baseline (speedup 1.0000x reference)
#include <cuda_runtime.h>

#define Bsz 64
#define Dd  512
#define Ll  8192
#define NLn 1000

// Intermediates (device globals; no allocations allowed)
__device__ __align__(16) float g_ye0[Bsz*Dd];
__device__ __align__(16) float g_ye1[Bsz*Dd];
__device__ __align__(16) float g_ye2[Bsz*Dd];
__device__ __align__(16) float g_zz1[Bsz*Dd];
__device__ __align__(16) float g_zz2[Bsz*Dd];
__device__ __align__(16) float g_s[Bsz];

__device__ __forceinline__ void cp_async16(void* dst, const void* src) {
    unsigned s = (unsigned)__cvta_generic_to_shared(dst);
    asm volatile("cp.async.cg.shared.global [%0], [%1], 16;" :: "r"(s), "l"(src) : "memory");
}

// ---------------------------------------------------------------------------
// K1: gather ye0 = W_yemb[:, y[b]] + b_yemb, and init residual targets:
//     g_ye1 = ye0 + by1 ; g_zz1 = z + bz1
// ---------------------------------------------------------------------------
__global__ void k_prep(const float* __restrict__ z, const int* __restrict__ y,
                       const float* __restrict__ W_yemb, const float* __restrict__ b_yemb,
                       const float* __restrict__ by1, const float* __restrict__ bz1) {
    int b = blockIdx.x, e = threadIdx.x;
    int yb = y[b];
    float v = W_yemb[e*NLn + yb] + b_yemb[e];
    g_ye0[b*Dd+e] = v;
    g_ye1[b*Dd+e] = v + by1[e];
    g_zz1[b*Dd+e] = z[b*Dd+e] + bz1[e];
}

// K3: init stage-2 residual targets: g_ye2 = ye1 + by2 ; g_zz2 = zz1 + bz2
__global__ void k_init2(const float* __restrict__ by2, const float* __restrict__ bz2) {
    int b = blockIdx.x, e = threadIdx.x;
    g_ye2[b*Dd+e] = g_ye1[b*Dd+e] + by2[e];
    g_zz2[b*Dd+e] = g_zz1[b*Dd+e] + bz2[e];
}

// ---------------------------------------------------------------------------
// Small residual GEMM: C += A @ W^T  (A [64,512], W [512,512], both row-major)
// CTA tile: 64b x 32e, split-K=4 (K-chunk 128), atomicAdd into pre-initialized C.
// grid (64, 2): x = e-tile(16) x ksplit(4); y selects the (ye, zz) problem.
// 128 threads; thread tile 4b x 4e; XOR-swizzled smem (conflict-free f4 reads).
// ---------------------------------------------------------------------------
template<int STAGE>
__global__ void __launch_bounds__(128) k_small(const float* __restrict__ zin,
                                               const float* __restrict__ Wy,
                                               const float* __restrict__ Wz) {
    __shared__ float4 As[64*32];   // A chunk [64][128] swizzled
    __shared__ float4 Ws[32*32];   // W chunk [32][128] swizzled
    const float* A; const float* W; float* C;
    if (STAGE == 1) {
        if (blockIdx.y == 0) { A = g_ye0; W = Wy; C = g_ye1; }
        else                 { A = zin;   W = Wz; C = g_zz1; }
    } else {
        if (blockIdx.y == 0) { A = g_ye1; W = Wy; C = g_ye2; }
        else                 { A = g_zz1; W = Wz; C = g_zz2; }
    }
    const int t  = threadIdx.x;
    const int e0 = (blockIdx.x & 15) * 32;
    const int k0 = (blockIdx.x >> 4) * 128;

    for (int idx = t; idx < 64*32; idx += 128) {
        int row = idx >> 5, k4 = idx & 31;
        As[row*32 + (k4 ^ (row & 7))] = *(const float4*)(A + row*Dd + k0 + k4*4);
    }
    for (int idx = t; idx < 32*32; idx += 128) {
        int row = idx >> 5, k4 = idx & 31;
        Ws[row*32 + (k4 ^ (row & 7))] = *(const float4*)(W + (e0+row)*Dd + k0 + k4*4);
    }
    __syncthreads();

    const int ec = t & 7;    // e = e0 + ec + 8j  -> e&7 == ec
    const int bg = t >> 3;   // b = bg + 16i      -> b&7 == bg&7
    float acc[4][4] = {};
    #pragma unroll 8
    for (int k4 = 0; k4 < 32; k4++) {
        float4 a[4], w[4];
        #pragma unroll
        for (int i = 0; i < 4; i++) a[i] = As[(bg + 16*i)*32 + (k4 ^ (bg & 7))];
        #pragma unroll
        for (int j = 0; j < 4; j++) w[j] = Ws[(ec +  8*j)*32 + (k4 ^ ec)];
        #pragma unroll
        for (int i = 0; i < 4; i++)
            #pragma unroll
            for (int j = 0; j < 4; j++)
                acc[i][j] += a[i].x*w[j].x + a[i].y*w[j].y
                           + a[i].z*w[j].z + a[i].w*w[j].w;
    }
    #pragma unroll
    for (int i = 0; i < 4; i++)
        #pragma unroll
        for (int j = 0; j < 4; j++)
            atomicAdd(&C[(bg + 16*i)*Dd + e0 + ec + 8*j], acc[i][j]);
}

// K5: s[b] = dot(ye2[b], w_proj)
__global__ void k_sproj(const float* __restrict__ w_proj) {
    int b = blockIdx.x, t = threadIdx.x;
    float p = 0.f;
    for (int e = t; e < Dd; e += 128) p += g_ye2[b*Dd+e] * w_proj[e];
    #pragma unroll
    for (int o = 16; o; o >>= 1) p += __shfl_down_sync(0xffffffffu, p, o);
    __shared__ float sm[4];
    if ((t & 31) == 0) sm[t >> 5] = p;
    __syncthreads();
    if (t == 0) g_s[b] = sm[0] + sm[1] + sm[2] + sm[3];
}

// ---------------------------------------------------------------------------
// K6: out[b,l] = s[b] * dot(zz2[b,:], W_zlat[l,:])
// CTA: 64b x 64l, 128 threads, thread tile 8b x 4l (1.5 B LDS / FMA -> FFMA-bound).
// cp.async double-buffered K-chunks of 32, XOR-swizzled smem.
// ---------------------------------------------------------------------------
__global__ void __launch_bounds__(128) k_big(const float* __restrict__ Wz,
                                             float* __restrict__ out) {
    __shared__ float4 As[2][512];   // [buf][64 rows x 8 f4] swizzled
    __shared__ float4 Ws[2][512];
    const int t  = threadIdx.x;
    const int l0 = blockIdx.x * 64;
    const int lc = t & 15;          // l = l0 + lc + 16j -> l&7 == lc&7
    const int bg = t >> 4;          // b = bg + 8i       -> b&7 == bg
    float acc[8][4] = {};

    auto load = [&](int buf, int c) {
        #pragma unroll
        for (int r = 0; r < 4; r++) {
            int idx = t + 128*r;            // 0..511
            int row = idx >> 3, k4 = idx & 7;
            int sidx = row*8 + (k4 ^ (row & 7));
            cp_async16(&As[buf][sidx], g_zz2 + row*Dd + c*32 + k4*4);
            cp_async16(&Ws[buf][sidx], Wz + (l0+row)*Dd + c*32 + k4*4);
        }
        asm volatile("cp.async.commit_group;" ::: "memory");
    };

    load(0, 0);
    #pragma unroll 1
    for (int c = 0; c < 16; c++) {
        if (c < 15) {
            load((c+1) & 1, c+1);
            asm volatile("cp.async.wait_group 1;" ::: "memory");
        } else {
            asm volatile("cp.async.wait_group 0;" ::: "memory");
        }
        __syncthreads();
        const float4* Ab = As[c & 1];
        const float4* Wb = Ws[c & 1];
        #pragma unroll
        for (int k4 = 0; k4 < 8; k4++) {
            float4 a[8], w[4];
            #pragma unroll
            for (int i = 0; i < 8; i++) a[i] = Ab[(bg + 8*i)*8 + (k4 ^ bg)];
            #pragma unroll
            for (int j = 0; j < 4; j++) w[j] = Wb[(lc + 16*j)*8 + (k4 ^ (lc & 7))];
            #pragma unroll
            for (int i = 0; i < 8; i++)
                #pragma unroll
                for (int j = 0; j < 4; j++) {
                    acc[i][j] += a[i].x*w[j].x;
                    acc[i][j] += a[i].y*w[j].y;
                    acc[i][j] += a[i].z*w[j].z;
                    acc[i][j] += a[i].w*w[j].w;
                }
        }
        __syncthreads();
    }
    #pragma unroll
    for (int i = 0; i < 8; i++) {
        float s = g_s[bg + 8*i];
        #pragma unroll
        for (int j = 0; j < 4; j++)
            out[(bg + 8*i)*Ll + l0 + lc + 16*j] = acc[i][j] * s;
    }
}

extern "C" void kernel_launch(void* const* d_in, const int* in_sizes, int n_in,
                              void* d_out, int out_size) {
    const float* z      = (const float*)d_in[0];
    const int*   y      = (const int*)  d_in[1];
    const float* W_yemb = (const float*)d_in[2];
    const float* b_yemb = (const float*)d_in[3];
    const float* Wy1    = (const float*)d_in[4];
    const float* by1    = (const float*)d_in[5];
    const float* Wy2    = (const float*)d_in[6];
    const float* by2    = (const float*)d_in[7];
    const float* Wz1    = (const float*)d_in[8];
    const float* bz1    = (const float*)d_in[9];
    const float* Wz2    = (const float*)d_in[10];
    const float* bz2    = (const float*)d_in[11];
    const float* W_zlat = (const float*)d_in[12];
    const float* w_proj = (const float*)d_in[13];
    float* out = (float*)d_out;

    k_prep<<<Bsz, Dd>>>(z, y, W_yemb, b_yemb, by1, bz1);
    k_small<1><<<dim3(64, 2), 128>>>(z, Wy1, Wz1);
    k_init2<<<Bsz, Dd>>>(by2, bz2);
    k_small<2><<<dim3(64, 2), 128>>>(nullptr, Wy2, Wz2);
    k_sproj<<<Bsz, 128>>>(w_proj);
    k_big<<<Ll/64, 128>>>(W_zlat, out);
}

// round 2
// speedup vs baseline: 1.0953x; 1.0953x over previous
#include <cuda_runtime.h>

#define Bsz 64
#define Dd  512
#define Ll  8192
#define NLn 1000

typedef unsigned long long ull;

// Intermediates (device globals; allocations forbidden)
__device__ __align__(16) float g_ye0T[Dd*Bsz];   // k-major
__device__ __align__(16) float g_zT  [Dd*Bsz];   // k-major
__device__ __align__(16) float g_ye1 [Bsz*Dd];
__device__ __align__(16) float g_zz1 [Bsz*Dd];
__device__ __align__(16) float g_ye1T[Dd*Bsz];
__device__ __align__(16) float g_zz1T[Dd*Bsz];
__device__ __align__(16) float g_ye2 [Bsz*Dd];
__device__ __align__(16) float g_zz2 [Bsz*Dd];
__device__ __align__(16) float g_zz2T[Dd*Bsz];   // k-major for k_big
__device__ __align__(16) float g_s[Bsz];

__device__ __forceinline__ void cp_async16(void* dst, const void* src) {
    unsigned s = (unsigned)__cvta_generic_to_shared(dst);
    asm volatile("cp.async.cg.shared.global [%0], [%1], 16;" :: "r"(s), "l"(src) : "memory");
}
__device__ __forceinline__ ull pack2(float lo, float hi) {
    ull r; asm("mov.b64 %0, {%1, %2};" : "=l"(r) : "f"(lo), "f"(hi)); return r;
}
__device__ __forceinline__ void unpack2(float& lo, float& hi, ull v) {
    asm("mov.b64 {%0, %1}, %2;" : "=f"(lo), "=f"(hi) : "l"(v));
}
__device__ __forceinline__ void ffma2(ull& d, ull a, ull b) {
    asm("fma.rn.f32x2 %0, %1, %2, %0;" : "+l"(d) : "l"(a), "l"(b));
}
__device__ __forceinline__ ull fmul2(ull a, ull b) {
    ull r; asm("mul.rn.f32x2 %0, %1, %2;" : "=l"(r) : "l"(a), "l"(b)); return r;
}

// ---------------------------------------------------------------------------
// K1: gather ye0 = W_yemb[:, y[b]] + b_yemb (store k-major), zT (k-major),
//     and init residual targets g_ye1 = ye0 + by1, g_zz1 = z + bz1.
// ---------------------------------------------------------------------------
__global__ void k_prep(const float* __restrict__ z, const int* __restrict__ y,
                       const float* __restrict__ W_yemb, const float* __restrict__ b_yemb,
                       const float* __restrict__ by1, const float* __restrict__ bz1) {
    int b = blockIdx.x, e = threadIdx.x;
    int yb = y[b];
    float v  = W_yemb[e*NLn + yb] + b_yemb[e];
    float zv = z[b*Dd + e];
    g_ye0T[e*Bsz + b] = v;
    g_zT  [e*Bsz + b] = zv;
    g_ye1 [b*Dd + e]  = v  + by1[e];
    g_zz1 [b*Dd + e]  = zv + bz1[e];
}

// K3: stage-2 residual init + transposes of the now-complete stage-1 outputs
__global__ void k_init2(const float* __restrict__ by2, const float* __restrict__ bz2) {
    int b = blockIdx.x, e = threadIdx.x;
    float v1 = g_ye1[b*Dd + e];
    float w1 = g_zz1[b*Dd + e];
    g_ye2 [b*Dd + e]  = v1 + by2[e];
    g_zz2 [b*Dd + e]  = w1 + bz2[e];
    g_ye1T[e*Bsz + b] = v1;
    g_zz1T[e*Bsz + b] = w1;
}

// ---------------------------------------------------------------------------
// Small residual GEMM: C += A @ W^T   (A [64,512] given k-major as AT, W [512,512])
// CTA: 64b x 32e, k-chunk 64, split-K=8. grid (16*8, 2), 256 threads.
// FFMA2: acc pairs over b. Single-shot smem chunk (24KB), 8 atomics/thread.
// ---------------------------------------------------------------------------
template<int STAGE>
__global__ void __launch_bounds__(256) k_small(const float* __restrict__ Wy,
                                               const float* __restrict__ Wz) {
    __shared__ float sA[64*64];   // [k][b]   16KB, contiguous copy
    __shared__ float sW[32*64];   // [e][k]   8KB, 16B-block XOR swizzled
    const float* A; const float* W; float* C;
    if (STAGE == 1) {
        if (blockIdx.y == 0) { A = g_ye0T; W = Wy; C = g_ye1; }
        else                 { A = g_zT;   W = Wz; C = g_zz1; }
    } else {
        if (blockIdx.y == 0) { A = g_ye1T; W = Wy; C = g_ye2; }
        else                 { A = g_zz1T; W = Wz; C = g_zz2; }
    }
    const int t  = threadIdx.x;
    const int e0 = (blockIdx.x & 15) * 32;
    const int k0 = (blockIdx.x >> 4) * 64;

    // A chunk: rows k0..k0+63 of AT -> contiguous 16KB
    #pragma unroll
    for (int r = 0; r < 4; r++)
        cp_async16(&sA[(t + 256*r)*4], A + k0*Bsz + (t + 256*r)*4);
    // W chunk: 32 e-rows x 64 k, swizzled in 16B blocks
    #pragma unroll
    for (int r = 0; r < 2; r++) {
        int idx = t + 256*r;            // 0..511
        int e = idx >> 4, k4 = idx & 15;
        cp_async16(&sW[e*64 + ((k4 ^ (e & 15)) << 2)],
                   W + (e0 + e)*Dd + k0 + 4*k4);
    }
    asm volatile("cp.async.commit_group;" ::: "memory");
    asm volatile("cp.async.wait_group 0;" ::: "memory");
    __syncthreads();

    const int ec = t & 15;      // e = e0 + ec, e0 + 16 + ec
    const int bg = t >> 4;      // b = 4bg..4bg+3 (2 pairs)
    ull acc00 = 0, acc10 = 0, acc01 = 0, acc11 = 0;

    #pragma unroll 4
    for (int k = 0; k < 64; k++) {
        ulonglong2 av = *(const ulonglong2*)&sA[k*Bsz + 4*bg];
        int sw = (((k >> 2) ^ ec) << 2) + (k & 3);
        float w0 = sW[ec*64 + sw];
        float w1 = sW[(ec + 16)*64 + sw];   // (ec+16)&15 == ec
        ull wp0 = pack2(w0, w0), wp1 = pack2(w1, w1);
        ffma2(acc00, av.x, wp0); ffma2(acc10, av.y, wp0);
        ffma2(acc01, av.x, wp1); ffma2(acc11, av.y, wp1);
    }

    float lo, hi;
    int b0 = 4*bg;
    unpack2(lo, hi, acc00);
    atomicAdd(&C[(b0+0)*Dd + e0 + ec],      lo);
    atomicAdd(&C[(b0+1)*Dd + e0 + ec],      hi);
    unpack2(lo, hi, acc10);
    atomicAdd(&C[(b0+2)*Dd + e0 + ec],      lo);
    atomicAdd(&C[(b0+3)*Dd + e0 + ec],      hi);
    unpack2(lo, hi, acc01);
    atomicAdd(&C[(b0+0)*Dd + e0 + 16 + ec], lo);
    atomicAdd(&C[(b0+1)*Dd + e0 + 16 + ec], hi);
    unpack2(lo, hi, acc11);
    atomicAdd(&C[(b0+2)*Dd + e0 + 16 + ec], lo);
    atomicAdd(&C[(b0+3)*Dd + e0 + 16 + ec], hi);
}

// K5: s[b] = dot(ye2[b], w_proj); also transpose zz2 -> zz2T for k_big
__global__ void k_sproj(const float* __restrict__ w_proj) {
    int b = blockIdx.x, t = threadIdx.x;
    float p = 0.f;
    for (int e = t; e < Dd; e += 128) {
        float v = g_zz2[b*Dd + e];
        g_zz2T[e*Bsz + b] = v;
        p += g_ye2[b*Dd + e] * w_proj[e];
    }
    #pragma unroll
    for (int o = 16; o; o >>= 1) p += __shfl_down_sync(0xffffffffu, p, o);
    __shared__ float sm[4];
    if ((t & 31) == 0) sm[t >> 5] = p;
    __syncthreads();
    if (t == 0) g_s[b] = sm[0] + sm[1] + sm[2] + sm[3];
}

// ---------------------------------------------------------------------------
// K6: out[b,l] = s[b] * dot(zz2[b,:], W_zlat[l,:])
// CTA: 64b x 32l, 128 threads, thread 8b x 2l as 8 FFMA2 accumulators.
// Double-buffered cp.async (A from zz2T contiguous, W swizzled 16B blocks).
// ---------------------------------------------------------------------------
__global__ void __launch_bounds__(128) k_big(const float* __restrict__ Wz,
                                             float* __restrict__ out) {
    __shared__ float sA[2][32*64];   // [k][b]  8KB each
    __shared__ float sW[2][32*32];   // [l][k]  4KB each, swizzled
    const int t  = threadIdx.x;
    const int l0 = blockIdx.x * 32;
    const int lc = t & 15;           // l = l0+lc, l0+16+lc
    const int bg = t >> 4;           // b = 4bg..4bg+3 and 32+4bg..+3

    auto load = [&](int buf, int c) {
        #pragma unroll
        for (int r = 0; r < 4; r++)
            cp_async16(&sA[buf][(t + 128*r)*4], g_zz2T + c*32*Bsz + (t + 128*r)*4);
        #pragma unroll
        for (int r = 0; r < 2; r++) {
            int idx = t + 128*r;      // 0..255
            int l = idx >> 3, k4 = idx & 7;
            cp_async16(&sW[buf][l*32 + ((k4 ^ (l & 7)) << 2)],
                       Wz + (l0 + l)*Dd + c*32 + 4*k4);
        }
        asm volatile("cp.async.commit_group;" ::: "memory");
    };

    ull acc[4][2];
    #pragma unroll
    for (int i = 0; i < 4; i++) { acc[i][0] = 0; acc[i][1] = 0; }

    load(0, 0);
    #pragma unroll 1
    for (int c = 0; c < 16; c++) {
        if (c < 15) {
            load((c + 1) & 1, c + 1);
            asm volatile("cp.async.wait_group 1;" ::: "memory");
        } else {
            asm volatile("cp.async.wait_group 0;" ::: "memory");
        }
        __syncthreads();
        const float* Ab = sA[c & 1];
        const float* Wb = sW[c & 1];
        #pragma unroll 4
        for (int k = 0; k < 32; k++) {
            ulonglong2 a01 = *(const ulonglong2*)&Ab[k*Bsz + 4*bg];
            ulonglong2 a23 = *(const ulonglong2*)&Ab[k*Bsz + 32 + 4*bg];
            int sw = (((k >> 2) ^ (lc & 7)) << 2) + (k & 3);
            float w0 = Wb[lc*32 + sw];
            float w1 = Wb[(lc + 16)*32 + sw];   // (lc+16)&7 == lc&7
            ull wp0 = pack2(w0, w0), wp1 = pack2(w1, w1);
            ffma2(acc[0][0], a01.x, wp0); ffma2(acc[1][0], a01.y, wp0);
            ffma2(acc[2][0], a23.x, wp0); ffma2(acc[3][0], a23.y, wp0);
            ffma2(acc[0][1], a01.x, wp1); ffma2(acc[1][1], a01.y, wp1);
            ffma2(acc[2][1], a23.x, wp1); ffma2(acc[3][1], a23.y, wp1);
        }
        __syncthreads();
    }

    // scale by s[b] and store (pairs over b -> s pairs; 16 STG.32)
    float2 sl = *(const float2*)&g_s[4*bg];
    float2 sh = *(const float2*)&g_s[4*bg + 2];
    float2 tl = *(const float2*)&g_s[32 + 4*bg];
    float2 th = *(const float2*)&g_s[32 + 4*bg + 2];
    ull sp[4] = { pack2(sl.x, sl.y), pack2(sh.x, sh.y),
                  pack2(tl.x, tl.y), pack2(th.x, th.y) };
    int bb[4] = { 4*bg, 4*bg + 2, 32 + 4*bg, 32 + 4*bg + 2 };
    #pragma unroll
    for (int p = 0; p < 4; p++) {
        #pragma unroll
        for (int j = 0; j < 2; j++) {
            float lo, hi;
            unpack2(lo, hi, fmul2(acc[p][j], sp[p]));
            out[(bb[p] + 0)*Ll + l0 + 16*j + lc] = lo;
            out[(bb[p] + 1)*Ll + l0 + 16*j + lc] = hi;
        }
    }
}

extern "C" void kernel_launch(void* const* d_in, const int* in_sizes, int n_in,
                              void* d_out, int out_size) {
    const float* z      = (const float*)d_in[0];
    const int*   y      = (const int*)  d_in[1];
    const float* W_yemb = (const float*)d_in[2];
    const float* b_yemb = (const float*)d_in[3];
    const float* Wy1    = (const float*)d_in[4];
    const float* by1    = (const float*)d_in[5];
    const float* Wy2    = (const float*)d_in[6];
    const float* by2    = (const float*)d_in[7];
    const float* Wz1    = (const float*)d_in[8];
    const float* bz1    = (const float*)d_in[9];
    const float* Wz2    = (const float*)d_in[10];
    const float* bz2    = (const float*)d_in[11];
    const float* W_zlat = (const float*)d_in[12];
    const float* w_proj = (const float*)d_in[13];
    float* out = (float*)d_out;

    k_prep<<<Bsz, Dd>>>(z, y, W_yemb, b_yemb, by1, bz1);
    k_small<1><<<dim3(128, 2), 256>>>(Wy1, Wz1);
    k_init2<<<Bsz, Dd>>>(by2, bz2);
    k_small<2><<<dim3(128, 2), 256>>>(Wy2, Wz2);
    k_sproj<<<Bsz, 128>>>(w_proj);
    k_big<<<Ll/32, 128>>>(W_zlat, out);
}